// round 13
// baseline (speedup 1.0000x reference)
#include <cuda_runtime.h>
#include <cuda_bf16.h>
#include <cstdint>

#define NB      16384
#define ADIM    32
#define KTOT    2048
#define EDIM    128
#define NACT    1000
#define ODIM    64

#define KC      64                 // K per chunk (bf16 elems)
#define NCHUNK  (KTOT / KC)        // 32
#define PITCH   72                 // bf16 per smem row (144B) -> conflict-free ldmatrix
#define TILE_T  (64 * PITCH * 2)   // 9216 B per 64-row tile
#define BUF_B   (4 * TILE_T)       // Ah Al Bh Bl = 36864
#define DSMEM   (2 * BUF_B)        // 73728 (double buffer)
#define ATT_STRIDE 68              // floats; 272B rows -> conflict-free

// ---------------- scratch ----------------
__device__ float g_s_table[NACT];
__device__ float g_T2[NACT * ODIM];
__device__ float g_bias[ODIM];
__device__ __nv_bfloat16 g_Wt_h[ODIM * KTOT];   // Wfused^T hi, [o][k]
__device__ __nv_bfloat16 g_Wt_l[ODIM * KTOT];   // Wfused^T lo

// ---------------- helpers ----------------
__device__ __forceinline__ uint32_t smem_u32(const void* p) {
    uint32_t a;
    asm("{ .reg .u64 t; cvta.to.shared.u64 t, %1; cvt.u32.u64 %0, t; }"
        : "=r"(a) : "l"(p));
    return a;
}
__device__ __forceinline__ void ldsm_x4(uint32_t* r, uint32_t addr) {
    asm volatile("ldmatrix.sync.aligned.m8n8.x4.shared.b16 {%0,%1,%2,%3}, [%4];"
                 : "=r"(r[0]), "=r"(r[1]), "=r"(r[2]), "=r"(r[3]) : "r"(addr));
}
__device__ __forceinline__ void mma_bf16(float* c, const uint32_t* a, const uint32_t* b) {
    asm volatile(
        "mma.sync.aligned.m16n8k16.row.col.f32.bf16.bf16.f32 "
        "{%0,%1,%2,%3}, {%4,%5,%6,%7}, {%8,%9}, {%0,%1,%2,%3};"
        : "+f"(c[0]), "+f"(c[1]), "+f"(c[2]), "+f"(c[3])
        : "r"(a[0]), "r"(a[1]), "r"(a[2]), "r"(a[3]), "r"(b[0]), "r"(b[1]));
}
__device__ __forceinline__ void split2(float x, float y, uint32_t& hi, uint32_t& lo) {
    __nv_bfloat162 h = __floats2bfloat162_rn(x, y);
    __nv_bfloat162 l = __floats2bfloat162_rn(x - __low2float(h), y - __high2float(h));
    hi = *reinterpret_cast<uint32_t*>(&h);
    lo = *reinterpret_cast<uint32_t*>(&l);
}
__device__ __forceinline__ void cp16(uint32_t smem_dst, const void* gsrc) {
    asm volatile("cp.async.ca.shared.global [%0], [%1], 16;"
                 :: "r"(smem_dst), "l"(gsrc) : "memory");
}
__device__ __forceinline__ void cp_commit_wait() {
    asm volatile("cp.async.commit_group;" ::: "memory");
    asm volatile("cp.async.wait_group 0;" ::: "memory");
}

// ---------------------------------------------------------------------------
// prep_w: Wfused = W_state[2048,128] @ W_out[0:128, 0:64] (fp32),
//         stored transposed+split bf16 -> g_Wt_h/l [64][2048].
//         g_bias[o] = b_out[o] + b_state . W1[:,o]
// ---------------------------------------------------------------------------
__global__ void __launch_bounds__(256) prep_w_kernel(
    const float* __restrict__ W_state, const float* __restrict__ W_out,
    const float* __restrict__ b_state, const float* __restrict__ b_out)
{
    __shared__ float W1s[EDIM * ODIM];   // 32 KB
    __shared__ float Ast[16][EDIM];      // 8 KB

    const int tid = threadIdx.x;
    const int k0 = blockIdx.x * 16;

    #pragma unroll
    for (int i = 0; i < 32; i++)
        W1s[tid + i * 256] = W_out[tid + i * 256];
    for (int idx = tid; idx < 16 * EDIM; idx += 256) {
        const int r = idx >> 7, e = idx & 127;
        Ast[r][e] = W_state[(size_t)(k0 + r) * EDIM + e];
    }
    __syncthreads();

    const int o  = tid & 63;
    const int kk = tid >> 6;
    float acc[4];
    #pragma unroll
    for (int i = 0; i < 4; i++) {
        const int k = kk * 4 + i;
        float s = 0.f;
        #pragma unroll 8
        for (int e = 0; e < EDIM; e++)
            s = fmaf(Ast[k][e], W1s[e * ODIM + o], s);
        acc[i] = s;
    }
    uint2 hh, ll;
    split2(acc[0], acc[1], hh.x, ll.x);
    split2(acc[2], acc[3], hh.y, ll.y);
    const size_t base = (size_t)o * KTOT + k0 + kk * 4;
    *(uint2*)&g_Wt_h[base] = hh;
    *(uint2*)&g_Wt_l[base] = ll;

    if (blockIdx.x == 0 && tid < ODIM) {
        float b = b_out[tid];
        #pragma unroll 8
        for (int e = 0; e < EDIM; e++)
            b = fmaf(b_state[e], W1s[e * ODIM + tid], b);
        g_bias[tid] = b;
    }
}

// ---------------------------------------------------------------------------
// prep2: s_table + T2. grid 63 x 256.
// ---------------------------------------------------------------------------
__global__ void __launch_bounds__(256) prep2_kernel(
    const float* __restrict__ table, const float* __restrict__ W_att,
    const float* __restrict__ b_att, const float* __restrict__ W_out)
{
    __shared__ float Wo2[EDIM * ODIM];
    __shared__ float rows[16][EDIM];
    __shared__ float watt[EDIM];

    const int tid = threadIdx.x;
    #pragma unroll
    for (int i = 0; i < 32; i++)
        Wo2[tid + i * 256] = W_out[EDIM * ODIM + tid + i * 256];
    if (tid < EDIM) watt[tid] = W_att[tid];

    const int r0 = blockIdx.x * 16;
    for (int idx = tid; idx < 16 * EDIM; idx += 256) {
        const int r = idx >> 7, e = idx & 127;
        rows[r][e] = (r0 + r < NACT) ? table[(size_t)(r0 + r) * EDIM + e] : 0.f;
    }
    __syncthreads();

    if (tid < 16 && r0 + tid < NACT) {
        float s = 0.f;
        #pragma unroll 8
        for (int e = 0; e < EDIM; e++) s = fmaf(rows[tid][e], watt[e], s);
        g_s_table[r0 + tid] = s + b_att[0];
    }

    #pragma unroll
    for (int i = 0; i < 4; i++) {
        const int idx = tid + i * 256;
        const int r = idx >> 6, o = idx & 63;
        if (r0 + r < NACT) {
            float acc = 0.f;
            #pragma unroll 8
            for (int e = 0; e < EDIM; e++)
                acc = fmaf(rows[r][e], Wo2[e * ODIM + o], acc);
            g_T2[(size_t)(r0 + r) * ODIM + o] = acc;
        }
    }
}

// ---------------------------------------------------------------------------
// gemm_fused: out = state @ Wfused + g_bias + attention(T2).
// CTA 64x64, 8 warps (2m x 4n), KC=64 double-buffered, cp.async B,
// fused softmax+T2-gather epilogue. grid 256, 2 CTAs/SM.
// ---------------------------------------------------------------------------
__global__ void __launch_bounds__(256, 2)
gemm_fused_kernel(const float* __restrict__ state,
                  const int* __restrict__ action,
                  float* __restrict__ out)
{
    extern __shared__ __align__(128) char dsm[];
    const uint32_t dyn = smem_u32(dsm);

    const int tid = threadIdx.x;
    const int wid = tid >> 5, lane = tid & 31;
    const int warp_m = wid & 1;          // 2 x 32 rows
    const int warp_n = wid >> 1;         // 4 x 16 cols
    const int rowBase = blockIdx.x * 64;

    // fills: 4 threads per row, 16 k each
    const int frow = tid >> 2;           // 0..63
    const int fseg = (tid & 3) * 16;     // 0,16,32,48
    const float* asrc = state + (size_t)(rowBase + frow) * KTOT + fseg;
    const __nv_bfloat16* bh_src = g_Wt_h + (size_t)frow * KTOT + fseg;
    const __nv_bfloat16* bl_src = g_Wt_l + (size_t)frow * KTOT + fseg;
    const uint32_t foff = frow * (PITCH * 2) + fseg * 2;   // byte offset

    const int lg = lane >> 3, lr = lane & 7;

    float acc[2][2][4];
    #pragma unroll
    for (int mi = 0; mi < 2; mi++)
        #pragma unroll
        for (int j = 0; j < 2; j++)
            #pragma unroll
            for (int q = 0; q < 4; q++) acc[mi][j][q] = 0.f;

    // ---- prologue: fill buffer 0 ----
    {
        cp16(dyn + 2 * TILE_T + foff,      bh_src);
        cp16(dyn + 2 * TILE_T + foff + 16, bh_src + 8);
        cp16(dyn + 3 * TILE_T + foff,      bl_src);
        cp16(dyn + 3 * TILE_T + foff + 16, bl_src + 8);
        char* base = dsm;
        #pragma unroll
        for (int i = 0; i < 2; i++) {
            float4 v0 = __ldg((const float4*)(asrc + i * 8));
            float4 v1 = __ldg((const float4*)(asrc + i * 8 + 4));
            uint4 hh, ll;
            split2(v0.x, v0.y, hh.x, ll.x);
            split2(v0.z, v0.w, hh.y, ll.y);
            split2(v1.x, v1.y, hh.z, ll.z);
            split2(v1.z, v1.w, hh.w, ll.w);
            *(uint4*)(base + foff + i * 16)          = hh;
            *(uint4*)(base + TILE_T + foff + i * 16) = ll;
        }
        cp_commit_wait();
    }
    __syncthreads();

    for (int c = 0; c < NCHUNK; c++) {
        const int buf = c & 1;
        const uint32_t sb = dyn + buf * BUF_B;
        const bool pf = (c + 1 < NCHUNK);
        const uint32_t nbB = dyn + ((c + 1) & 1) * BUF_B;

        // kick off next B tiles via cp.async immediately
        float4 nA[4];
        if (pf) {
            const int k0 = (c + 1) * KC;
            cp16(nbB + 2 * TILE_T + foff,      bh_src + k0);
            cp16(nbB + 2 * TILE_T + foff + 16, bh_src + k0 + 8);
            cp16(nbB + 3 * TILE_T + foff,      bl_src + k0);
            cp16(nbB + 3 * TILE_T + foff + 16, bl_src + k0 + 8);
            #pragma unroll
            for (int i = 0; i < 4; i++)
                nA[i] = __ldg((const float4*)(asrc + k0 + i * 4));
        }

        const uint32_t sAh = sb, sAl = sb + TILE_T;
        const uint32_t sBh = sb + 2 * TILE_T, sBl = sb + 3 * TILE_T;

        #pragma unroll
        for (int s = 0; s < 4; s++) {
            uint32_t ah[2][4], al[2][4], bb[4];
            #pragma unroll
            for (int mi = 0; mi < 2; mi++) {
                const int arow = warp_m * 32 + mi * 16 + (lg & 1) * 8 + lr;
                const int acol = s * 16 + (lg >> 1) * 8;
                const uint32_t off = arow * (PITCH * 2) + acol * 2;
                ldsm_x4(ah[mi], sAh + off);
                ldsm_x4(al[mi], sAl + off);
            }
            const int nrow = warp_n * 16 + (lg >> 1) * 8 + lr;
            const int ncol = s * 16 + (lg & 1) * 8;
            ldsm_x4(bb, sBh + nrow * (PITCH * 2) + ncol * 2);
            #pragma unroll
            for (int mi = 0; mi < 2; mi++)
                #pragma unroll
                for (int j = 0; j < 2; j++)
                    mma_bf16(acc[mi][j], ah[mi], &bb[j * 2]);
            #pragma unroll
            for (int mi = 0; mi < 2; mi++)
                #pragma unroll
                for (int j = 0; j < 2; j++)
                    mma_bf16(acc[mi][j], al[mi], &bb[j * 2]);
            ldsm_x4(bb, sBl + nrow * (PITCH * 2) + ncol * 2);
            #pragma unroll
            for (int mi = 0; mi < 2; mi++)
                #pragma unroll
                for (int j = 0; j < 2; j++)
                    mma_bf16(acc[mi][j], ah[mi], &bb[j * 2]);
        }

        if (pf) {
            char* nb = dsm + ((c + 1) & 1) * BUF_B;
            #pragma unroll
            for (int i = 0; i < 2; i++) {
                uint4 hh, ll;
                split2(nA[2 * i].x,     nA[2 * i].y,     hh.x, ll.x);
                split2(nA[2 * i].z,     nA[2 * i].w,     hh.y, ll.y);
                split2(nA[2 * i + 1].x, nA[2 * i + 1].y, hh.z, ll.z);
                split2(nA[2 * i + 1].z, nA[2 * i + 1].w, hh.w, ll.w);
                *(uint4*)(nb + foff + i * 16)          = hh;
                *(uint4*)(nb + TILE_T + foff + i * 16) = ll;
            }
            cp_commit_wait();
        }
        __syncthreads();
    }

    // =========== fused attention epilogue ===========
    // Buffers are dead now; reuse dsm as att[64][ATT_STRIDE].
    float* att = (float*)dsm;

    // Warp w handles rows w*8 .. w*8+7; lane = action index.
    {
        #pragma unroll
        for (int rr = 0; rr < 8; rr++) {
            const int row = wid * 8 + rr;
            const int act = action[(size_t)(rowBase + row) * ADIM + lane];
            float s = g_s_table[act];
            float m = s;
            #pragma unroll
            for (int o = 16; o > 0; o >>= 1)
                m = fmaxf(m, __shfl_xor_sync(0xffffffffu, m, o));
            float p = __expf(s - m);
            float sum = p;
            #pragma unroll
            for (int o = 16; o > 0; o >>= 1)
                sum += __shfl_xor_sync(0xffffffffu, sum, o);
            const float wgt = p / sum;

            float a0 = 0.f, a1 = 0.f;
            #pragma unroll 4
            for (int a = 0; a < 32; a++) {
                const int id  = __shfl_sync(0xffffffffu, act, a);
                const float wa = __shfl_sync(0xffffffffu, wgt, a);
                const float2 t2 = *(const float2*)&g_T2[(size_t)id * ODIM + 2 * lane];
                a0 = fmaf(wa, t2.x, a0);
                a1 = fmaf(wa, t2.y, a1);
            }
            *(float2*)&att[row * ATT_STRIDE + 2 * lane] = make_float2(a0, a1);
        }
    }
    __syncthreads();

    // ---- bias + att + store ----
    const int cbase = warp_n * 16 + (lane & 3) * 2;
    float2 bias[2];
    #pragma unroll
    for (int j = 0; j < 2; j++)
        bias[j] = *(const float2*)&g_bias[cbase + j * 8];

    #pragma unroll
    for (int mi = 0; mi < 2; mi++) {
        const int lr0 = warp_m * 32 + mi * 16 + (lane >> 2);   // local row
        const size_t r0 = rowBase + lr0;
        #pragma unroll
        for (int j = 0; j < 2; j++) {
            const int col = cbase + j * 8;
            const float2 at0 = *(const float2*)&att[lr0 * ATT_STRIDE + col];
            const float2 at1 = *(const float2*)&att[(lr0 + 8) * ATT_STRIDE + col];
            float2 lo = make_float2(acc[mi][j][0] + bias[j].x + at0.x,
                                    acc[mi][j][1] + bias[j].y + at0.y);
            float2 hi = make_float2(acc[mi][j][2] + bias[j].x + at1.x,
                                    acc[mi][j][3] + bias[j].y + at1.y);
            *(float2*)&out[r0 * ODIM + col]       = lo;
            *(float2*)&out[(r0 + 8) * ODIM + col] = hi;
        }
    }
}

// ---------------------------------------------------------------------------
extern "C" void kernel_launch(void* const* d_in, const int* in_sizes, int n_in,
                              void* d_out, int out_size)
{
    const float* state   = (const float*)d_in[0];
    const int*   action  = (const int*)  d_in[1];
    const float* W_state = (const float*)d_in[2];
    const float* b_state = (const float*)d_in[3];
    const float* table   = (const float*)d_in[4];
    const float* W_att   = (const float*)d_in[5];
    const float* b_att   = (const float*)d_in[6];
    const float* W_out   = (const float*)d_in[7];
    const float* b_out   = (const float*)d_in[8];
    float* out = (float*)d_out;

    cudaFuncSetAttribute(gemm_fused_kernel,
                         cudaFuncAttributeMaxDynamicSharedMemorySize, DSMEM);

    prep_w_kernel<<<KTOT / 16, 256>>>(W_state, W_out, b_state, b_out);
    prep2_kernel<<<(NACT + 15) / 16, 256>>>(table, W_att, b_att, W_out);
    gemm_fused_kernel<<<NB / 64, 256, DSMEM>>>(state, action, out);
}

// round 15
// speedup vs baseline: 1.0976x; 1.0976x over previous
#include <cuda_runtime.h>
#include <cuda_bf16.h>
#include <cstdint>

#define NB      16384
#define ADIM    32
#define KTOT    2048
#define EDIM    128
#define NACT    1000
#define ODIM    64

#define KC      32                 // K per chunk (bf16 elems)
#define NCHUNK  (KTOT / KC)        // 64
#define PITCH   40                 // bf16 per smem row (80B) -> conflict-free ldmatrix
#define TILE_T  (64 * PITCH * 2)   // 5120 B per 64-row tile
#define BUF_B   (4 * TILE_T)       // Ah Al Bh Bl = 20480
#define DSMEM   (2 * BUF_B)        // 40960 (double buffer)
#define ATT_STRIDE 68              // floats; conflict-free epilogue staging

#define PW_BLOCKS 256              // prep_w part: 8 k-rows per block
#define P2_BLOCKS 63               // prep2 part: 16 table rows per block

// ---------------- scratch ----------------
__device__ float g_s_table[NACT];
__device__ float g_T2[NACT * ODIM];
__device__ float g_bias[ODIM];
__device__ __nv_bfloat16 g_Wt_h[ODIM * KTOT];   // Wfused^T hi, [o][k]
__device__ __nv_bfloat16 g_Wt_l[ODIM * KTOT];   // Wfused^T lo

// ---------------- helpers ----------------
__device__ __forceinline__ uint32_t smem_u32(const void* p) {
    uint32_t a;
    asm("{ .reg .u64 t; cvta.to.shared.u64 t, %1; cvt.u32.u64 %0, t; }"
        : "=r"(a) : "l"(p));
    return a;
}
__device__ __forceinline__ void ldsm_x4(uint32_t* r, uint32_t addr) {
    asm volatile("ldmatrix.sync.aligned.m8n8.x4.shared.b16 {%0,%1,%2,%3}, [%4];"
                 : "=r"(r[0]), "=r"(r[1]), "=r"(r[2]), "=r"(r[3]) : "r"(addr));
}
__device__ __forceinline__ void mma_bf16(float* c, const uint32_t* a, const uint32_t* b) {
    asm volatile(
        "mma.sync.aligned.m16n8k16.row.col.f32.bf16.bf16.f32 "
        "{%0,%1,%2,%3}, {%4,%5,%6,%7}, {%8,%9}, {%0,%1,%2,%3};"
        : "+f"(c[0]), "+f"(c[1]), "+f"(c[2]), "+f"(c[3])
        : "r"(a[0]), "r"(a[1]), "r"(a[2]), "r"(a[3]), "r"(b[0]), "r"(b[1]));
}
__device__ __forceinline__ void split2(float x, float y, uint32_t& hi, uint32_t& lo) {
    __nv_bfloat162 h = __floats2bfloat162_rn(x, y);
    __nv_bfloat162 l = __floats2bfloat162_rn(x - __low2float(h), y - __high2float(h));
    hi = *reinterpret_cast<uint32_t*>(&h);
    lo = *reinterpret_cast<uint32_t*>(&l);
}

// ---------------------------------------------------------------------------
// prep_all: one launch, two independent jobs sharing ONE smem arena
// (branches never coexist; ptxas sums per-branch arrays, so alias manually).
//   blocks [0, PW_BLOCKS): Wfused split-bf16 (+ g_bias on block 0)
//   blocks [PW_BLOCKS, PW_BLOCKS+P2_BLOCKS): s_table + T2
// ---------------------------------------------------------------------------
#define PREP_SMEM 41472            // max(36864, 41472) bytes
__global__ void __launch_bounds__(256) prep_all_kernel(
    const float* __restrict__ W_state, const float* __restrict__ W_out,
    const float* __restrict__ b_state, const float* __restrict__ b_out,
    const float* __restrict__ table,   const float* __restrict__ W_att,
    const float* __restrict__ b_att)
{
    __shared__ __align__(16) char smbuf[PREP_SMEM];
    const int tid = threadIdx.x;

    if (blockIdx.x < PW_BLOCKS) {
        // ---------------- prep_w part ----------------
        float* W1s = (float*)smbuf;                       // [EDIM*ODIM] 32 KB
        float (*Ast)[EDIM] = (float(*)[EDIM])(smbuf + EDIM * ODIM * 4); // [8][128] 4 KB

        const int k0 = blockIdx.x * 8;
        #pragma unroll
        for (int i = 0; i < 32; i++)
            W1s[tid + i * 256] = W_out[tid + i * 256];
        for (int idx = tid; idx < 8 * EDIM; idx += 256) {
            const int r = idx >> 7, e = idx & 127;
            Ast[r][e] = W_state[(size_t)(k0 + r) * EDIM + e];
        }
        __syncthreads();

        const int o  = tid & 63;
        const int kk = tid >> 6;          // 0..3, 2 k each
        float a0 = 0.f, a1 = 0.f;
        #pragma unroll 8
        for (int e = 0; e < EDIM; e++) {
            const float w1 = W1s[e * ODIM + o];
            a0 = fmaf(Ast[kk * 2][e],     w1, a0);
            a1 = fmaf(Ast[kk * 2 + 1][e], w1, a1);
        }
        uint32_t hh, ll;
        split2(a0, a1, hh, ll);
        const size_t base = (size_t)o * KTOT + k0 + kk * 2;
        *(uint32_t*)&g_Wt_h[base] = hh;
        *(uint32_t*)&g_Wt_l[base] = ll;

        if (blockIdx.x == 0 && tid < ODIM) {
            float b = b_out[tid];
            #pragma unroll 8
            for (int e = 0; e < EDIM; e++)
                b = fmaf(b_state[e], W1s[e * ODIM + tid], b);
            g_bias[tid] = b;
        }
    } else {
        // ---------------- prep2 part ----------------
        float* Wo2 = (float*)smbuf;                              // 32 KB
        float (*rows)[EDIM] = (float(*)[EDIM])(smbuf + EDIM * ODIM * 4); // 8 KB
        float* watt = (float*)(smbuf + EDIM * ODIM * 4 + 16 * EDIM * 4); // 512 B

        const int r0 = (blockIdx.x - PW_BLOCKS) * 16;
        #pragma unroll
        for (int i = 0; i < 32; i++)
            Wo2[tid + i * 256] = W_out[EDIM * ODIM + tid + i * 256];
        if (tid < EDIM) watt[tid] = W_att[tid];
        for (int idx = tid; idx < 16 * EDIM; idx += 256) {
            const int r = idx >> 7, e = idx & 127;
            rows[r][e] = (r0 + r < NACT) ? table[(size_t)(r0 + r) * EDIM + e] : 0.f;
        }
        __syncthreads();

        if (tid < 16 && r0 + tid < NACT) {
            float s = 0.f;
            #pragma unroll 8
            for (int e = 0; e < EDIM; e++) s = fmaf(rows[tid][e], watt[e], s);
            g_s_table[r0 + tid] = s + b_att[0];
        }

        #pragma unroll
        for (int i = 0; i < 4; i++) {
            const int idx = tid + i * 256;
            const int r = idx >> 6, o = idx & 63;
            if (r0 + r < NACT) {
                float acc = 0.f;
                #pragma unroll 8
                for (int e = 0; e < EDIM; e++)
                    acc = fmaf(rows[r][e], Wo2[e * ODIM + o], acc);
                g_T2[(size_t)(r0 + r) * ODIM + o] = acc;
            }
        }
    }
}

// ---------------------------------------------------------------------------
// gemm_fused: out = state @ Wfused + g_bias + attention(T2).
// Mainloop = R12's proven KC=32 / PITCH=40 structure (CTA 64x64, 8 warps
// 2m x 4n, double-buffered, reg-staged fills, 2 CTAs/SM).
// Epilogue = fused softmax + T2 gather (smem-staged), single store to out.
// ---------------------------------------------------------------------------
__global__ void __launch_bounds__(256, 2)
gemm_fused_kernel(const float* __restrict__ state,
                  const int* __restrict__ action,
                  float* __restrict__ out)
{
    extern __shared__ __align__(128) char dsm[];
    const uint32_t dyn = smem_u32(dsm);

    const int tid = threadIdx.x;
    const int wid = tid >> 5, lane = tid & 31;
    const int warp_m = wid & 1;          // 2 x 32 rows
    const int warp_n = wid >> 1;         // 4 x 16 cols
    const int rowBase = blockIdx.x * 64;

    // fills: 4 threads per row, 8 k each
    const int frow = tid >> 2;           // 0..63
    const int fseg = (tid & 3) * 8;      // 0,8,16,24
    const float* asrc = state + (size_t)(rowBase + frow) * KTOT + fseg;
    const __nv_bfloat16* bh_src = g_Wt_h + (size_t)frow * KTOT + fseg;
    const __nv_bfloat16* bl_src = g_Wt_l + (size_t)frow * KTOT + fseg;
    const uint32_t foff = frow * (PITCH * 2) + fseg * 2;

    const int lg = lane >> 3, lr = lane & 7;

    float acc[2][2][4];
    #pragma unroll
    for (int mi = 0; mi < 2; mi++)
        #pragma unroll
        for (int j = 0; j < 2; j++)
            #pragma unroll
            for (int q = 0; q < 4; q++) acc[mi][j][q] = 0.f;

    // ---- prologue: fill buffer 0 ----
    {
        char* base = dsm;
        float4 v0 = __ldg((const float4*)asrc);
        float4 v1 = __ldg((const float4*)(asrc + 4));
        uint4 hh, ll;
        split2(v0.x, v0.y, hh.x, ll.x);
        split2(v0.z, v0.w, hh.y, ll.y);
        split2(v1.x, v1.y, hh.z, ll.z);
        split2(v1.z, v1.w, hh.w, ll.w);
        *(uint4*)(base + foff)              = hh;
        *(uint4*)(base + TILE_T + foff)     = ll;
        *(uint4*)(base + 2 * TILE_T + foff) = *(const uint4*)bh_src;
        *(uint4*)(base + 3 * TILE_T + foff) = *(const uint4*)bl_src;
    }
    __syncthreads();

    for (int c = 0; c < NCHUNK; c++) {
        const int buf = c & 1;
        const uint32_t sb = dyn + buf * BUF_B;

        float4 nA0, nA1;
        uint4 nBh, nBl;
        const bool pf = (c + 1 < NCHUNK);
        if (pf) {
            const int k0 = (c + 1) * KC;
            nA0 = __ldg((const float4*)(asrc + k0));
            nA1 = __ldg((const float4*)(asrc + k0 + 4));
            nBh = *(const uint4*)(bh_src + k0);
            nBl = *(const uint4*)(bl_src + k0);
        }

        const uint32_t sAh = sb, sAl = sb + TILE_T;
        const uint32_t sBh = sb + 2 * TILE_T, sBl = sb + 3 * TILE_T;

        #pragma unroll
        for (int s = 0; s < 2; s++) {
            uint32_t ah[2][4], al[2][4], bb[4];
            #pragma unroll
            for (int mi = 0; mi < 2; mi++) {
                const int arow = warp_m * 32 + mi * 16 + (lg & 1) * 8 + lr;
                const int acol = s * 16 + (lg >> 1) * 8;
                const uint32_t off = arow * (PITCH * 2) + acol * 2;
                ldsm_x4(ah[mi], sAh + off);
                ldsm_x4(al[mi], sAl + off);
            }
            const int nrow = warp_n * 16 + (lg >> 1) * 8 + lr;
            const int ncol = s * 16 + (lg & 1) * 8;
            ldsm_x4(bb, sBh + nrow * (PITCH * 2) + ncol * 2);
            #pragma unroll
            for (int mi = 0; mi < 2; mi++)
                #pragma unroll
                for (int j = 0; j < 2; j++)
                    mma_bf16(acc[mi][j], ah[mi], &bb[j * 2]);
            #pragma unroll
            for (int mi = 0; mi < 2; mi++)
                #pragma unroll
                for (int j = 0; j < 2; j++)
                    mma_bf16(acc[mi][j], al[mi], &bb[j * 2]);
            ldsm_x4(bb, sBl + nrow * (PITCH * 2) + ncol * 2);
            #pragma unroll
            for (int mi = 0; mi < 2; mi++)
                #pragma unroll
                for (int j = 0; j < 2; j++)
                    mma_bf16(acc[mi][j], ah[mi], &bb[j * 2]);
        }

        if (pf) {
            char* nb = dsm + ((c + 1) & 1) * BUF_B;
            uint4 hh, ll;
            split2(nA0.x, nA0.y, hh.x, ll.x);
            split2(nA0.z, nA0.w, hh.y, ll.y);
            split2(nA1.x, nA1.y, hh.z, ll.z);
            split2(nA1.z, nA1.w, hh.w, ll.w);
            *(uint4*)(nb + foff)              = hh;
            *(uint4*)(nb + TILE_T + foff)     = ll;
            *(uint4*)(nb + 2 * TILE_T + foff) = nBh;
            *(uint4*)(nb + 3 * TILE_T + foff) = nBl;
        }
        __syncthreads();
    }

    // =========== fused attention epilogue ===========
    // Buffers are dead now (last __syncthreads passed); reuse dsm.
    float* att = (float*)dsm;   // att[64][ATT_STRIDE] = 17408 B < DSMEM

    #pragma unroll
    for (int rr = 0; rr < 8; rr++) {
        const int row = wid * 8 + rr;
        const int act = action[(size_t)(rowBase + row) * ADIM + lane];
        float s = g_s_table[act];
        float m = s;
        #pragma unroll
        for (int o = 16; o > 0; o >>= 1)
            m = fmaxf(m, __shfl_xor_sync(0xffffffffu, m, o));
        float p = __expf(s - m);
        float sum = p;
        #pragma unroll
        for (int o = 16; o > 0; o >>= 1)
            sum += __shfl_xor_sync(0xffffffffu, sum, o);
        const float wgt = p / sum;

        float a0 = 0.f, a1 = 0.f;
        #pragma unroll 4
        for (int a = 0; a < 32; a++) {
            const int id  = __shfl_sync(0xffffffffu, act, a);
            const float wa = __shfl_sync(0xffffffffu, wgt, a);
            const float2 t2 = *(const float2*)&g_T2[(size_t)id * ODIM + 2 * lane];
            a0 = fmaf(wa, t2.x, a0);
            a1 = fmaf(wa, t2.y, a1);
        }
        *(float2*)&att[row * ATT_STRIDE + 2 * lane] = make_float2(a0, a1);
    }
    __syncthreads();

    // ---- bias + att + store ----
    const int cbase = warp_n * 16 + (lane & 3) * 2;
    float2 bias[2];
    #pragma unroll
    for (int j = 0; j < 2; j++)
        bias[j] = *(const float2*)&g_bias[cbase + j * 8];

    #pragma unroll
    for (int mi = 0; mi < 2; mi++) {
        const int lr0 = warp_m * 32 + mi * 16 + (lane >> 2);
        const size_t r0 = rowBase + lr0;
        #pragma unroll
        for (int j = 0; j < 2; j++) {
            const int col = cbase + j * 8;
            const float2 at0 = *(const float2*)&att[lr0 * ATT_STRIDE + col];
            const float2 at1 = *(const float2*)&att[(lr0 + 8) * ATT_STRIDE + col];
            float2 lo = make_float2(acc[mi][j][0] + bias[j].x + at0.x,
                                    acc[mi][j][1] + bias[j].y + at0.y);
            float2 hi = make_float2(acc[mi][j][2] + bias[j].x + at1.x,
                                    acc[mi][j][3] + bias[j].y + at1.y);
            *(float2*)&out[r0 * ODIM + col]       = lo;
            *(float2*)&out[(r0 + 8) * ODIM + col] = hi;
        }
    }
}

// ---------------------------------------------------------------------------
extern "C" void kernel_launch(void* const* d_in, const int* in_sizes, int n_in,
                              void* d_out, int out_size)
{
    const float* state   = (const float*)d_in[0];
    const int*   action  = (const int*)  d_in[1];
    const float* W_state = (const float*)d_in[2];
    const float* b_state = (const float*)d_in[3];
    const float* table   = (const float*)d_in[4];
    const float* W_att   = (const float*)d_in[5];
    const float* b_att   = (const float*)d_in[6];
    const float* W_out   = (const float*)d_in[7];
    const float* b_out   = (const float*)d_in[8];
    float* out = (float*)d_out;

    cudaFuncSetAttribute(gemm_fused_kernel,
                         cudaFuncAttributeMaxDynamicSharedMemorySize, DSMEM);

    prep_all_kernel<<<PW_BLOCKS + P2_BLOCKS, 256>>>(
        W_state, W_out, b_state, b_out, table, W_att, b_att);
    gemm_fused_kernel<<<NB / 64, 256, DSMEM>>>(state, action, out);
}